// round 2
// baseline (speedup 1.0000x reference)
#include <cuda_runtime.h>
#include <cstdint>

#define BB 256
#define MM 80
#define TT 1000
#define HH 128
#define GG (3*HH)   // 384

#define TILE_T 128
#define K1_THREADS 384
#define WPAD 385

#define K2_THREADS 768   // 2 k-halves x 384 g

// scratch: gx[b][t][g]  (393 MB)
__device__ float g_gx[(size_t)BB * TT * GG];

// ---------------- packed f32x2 helpers ----------------
__device__ __forceinline__ unsigned long long pack2(float lo, float hi) {
    unsigned long long r;
    asm("mov.b64 %0, {%1,%2};" : "=l"(r) : "f"(lo), "f"(hi));
    return r;
}
__device__ __forceinline__ void unpack2(unsigned long long v, float& lo, float& hi) {
    asm("mov.b64 {%0,%1}, %2;" : "=f"(lo), "=f"(hi) : "l"(v));
}
__device__ __forceinline__ unsigned long long ffma2(unsigned long long a,
                                                    unsigned long long b,
                                                    unsigned long long c) {
    unsigned long long d;
    asm("fma.rn.f32x2 %0, %1, %2, %3;" : "=l"(d) : "l"(a), "l"(b), "l"(c));
    return d;
}
__device__ __forceinline__ unsigned long long fadd2(unsigned long long a,
                                                    unsigned long long b) {
    unsigned long long d;
    asm("add.rn.f32x2 %0, %1, %2;" : "=l"(d) : "l"(a), "l"(b));
    return d;
}

__device__ __forceinline__ float fast_sigmoid(float x) {
    float e = __expf(-x);
    return __fdividef(1.0f, 1.0f + e);
}
__device__ __forceinline__ float fast_tanh(float x) {
    float ax = fabsf(x);
    float e = __expf(-2.0f * ax);
    float t = __fdividef(1.0f - e, 1.0f + e);
    return copysignf(t, x);
}

// ================= Kernel 1: gx = x^T @ W_ih^T + b_ih =================
__global__ __launch_bounds__(K1_THREADS)
void gx_kernel(const float* __restrict__ x,
               const float* __restrict__ W_ih,
               const float* __restrict__ b_ih)
{
    extern __shared__ float sm[];
    float* Wsh = sm;                         // [MM][WPAD] transposed (m-major)
    float* xsh = sm + MM * WPAD;             // [MM][TILE_T]
    const int tid = threadIdx.x;
    const int b   = blockIdx.y;
    const int t0  = blockIdx.x * TILE_T;

    for (int idx = tid; idx < GG * MM; idx += K1_THREADS) {
        int g = idx / MM, m = idx % MM;
        Wsh[m * WPAD + g] = W_ih[idx];
    }
    for (int idx = tid; idx < MM * TILE_T; idx += K1_THREADS) {
        int m = idx / TILE_T, tt = idx % TILE_T;
        int t = t0 + tt;
        xsh[m * TILE_T + tt] = (t < TT) ? x[((size_t)b * MM + m) * TT + t] : 0.0f;
    }
    __syncthreads();

    const int g = tid;
    const float bih = b_ih[g];
    const unsigned long long* xsh2 = (const unsigned long long*)xsh;

    for (int c = 0; c < TILE_T / 16; c++) {
        unsigned long long acc[8];
        #pragma unroll
        for (int i = 0; i < 8; i++) acc[i] = 0ULL;

        #pragma unroll 8
        for (int m = 0; m < MM; m++) {
            float w = Wsh[m * WPAD + g];
            unsigned long long w2 = pack2(w, w);
            const ulonglong2* xp = (const ulonglong2*)&xsh2[m * (TILE_T / 2) + c * 8];
            #pragma unroll
            for (int i = 0; i < 4; i++) {
                ulonglong2 xv = xp[i];
                acc[2 * i]     = ffma2(w2, xv.x, acc[2 * i]);
                acc[2 * i + 1] = ffma2(w2, xv.y, acc[2 * i + 1]);
            }
        }
        const int tbase = t0 + c * 16;
        #pragma unroll
        for (int i = 0; i < 8; i++) {
            float lo, hi;
            unpack2(acc[i], lo, hi);
            int t = tbase + 2 * i;
            if (t < TT)     g_gx[((size_t)b * TT + t) * GG + g]     = lo + bih;
            if (t + 1 < TT) g_gx[((size_t)b * TT + t + 1) * GG + g] = hi + bih;
        }
    }
}

// ================= Kernel 2: sequential GRU recurrence =================
// 128 blocks, 2 batches each, 768 threads. Thread (kh, g) holds W_hh[g][kh*64 .. kh*64+63]
// packed as 32 f32x2 (64 regs). Gate threads = tid < 256 (bb = tid>>7, j = tid&127).
__global__ __launch_bounds__(K2_THREADS, 1)
void gru_kernel(const float* __restrict__ W_hh,
                const float* __restrict__ b_hh,
                float* __restrict__ out)
{
    __shared__ __align__(16) float hs[2][HH];        // [batch][j]
    __shared__ float part[2][2][GG];                 // [kh][batch][g]

    const int tid = threadIdx.x;
    const int kh  = (tid >= 384) ? 1 : 0;
    const int g   = tid - kh * 384;
    const int b0  = blockIdx.x * 2;

    // gate role
    const int bb = (tid >> 7) & 1;     // valid when tid < 256
    const int j  = tid & (HH - 1);
    const bool is_gate = (tid < 256);

    // pack half a W_hh row into 32 f32x2 regs (reused for all 1000 steps)
    unsigned long long wreg[HH / 4];
    {
        const float4* wr = (const float4*)(W_hh + (size_t)g * HH + kh * (HH / 2));
        #pragma unroll
        for (int i = 0; i < HH / 8; i++) {
            float4 v = wr[i];
            wreg[2 * i]     = pack2(v.x, v.y);
            wreg[2 * i + 1] = pack2(v.z, v.w);
        }
    }
    // bias folded into kh==0 accumulator init
    const float bhg = (kh == 0) ? b_hh[g] : 0.0f;
    const unsigned long long bias2 = pack2(bhg, 0.0f);

    if (tid < 2 * HH) hs[bb][j] = 0.0f;

    // gate-side gx stream + registers
    const float* gxp = g_gx + ((size_t)(b0 + bb) * TT) * GG + j;
    float gxr = 0.f, gxz = 0.f, gxn = 0.f;
    float hreg = 0.0f;
    if (is_gate) {
        gxr = gxp[0];
        gxz = gxp[HH];
        gxn = gxp[2 * HH];
    }
    __syncthreads();

    const float* hbase0 = hs[0] + kh * (HH / 2);
    const float* hbase1 = hs[1] + kh * (HH / 2);
    float* p0 = &part[kh][0][g];
    float* p1 = &part[kh][1][g];

    for (int t = 0; t < TT; t++) {
        // prefetch next step's input-side gates (hidden under the dot product)
        float ngxr = 0.f, ngxz = 0.f, ngxn = 0.f;
        if (is_gate) {
            int tn = (t + 1 < TT) ? (t + 1) : (TT - 1);
            const float* p = gxp + (size_t)tn * GG;
            ngxr = p[0];
            ngxz = p[HH];
            ngxn = p[2 * HH];
        }

        unsigned long long a0 = bias2, a1 = 0ULL, a2 = bias2, a3 = 0ULL;
        const ulonglong2* h0v = (const ulonglong2*)hbase0;
        const ulonglong2* h1v = (const ulonglong2*)hbase1;
        #pragma unroll
        for (int i = 0; i < HH / 8; i++) {      // 16 iters: 32 LDS.128, 64 FFMA2
            ulonglong2 v0 = h0v[i];
            ulonglong2 v1 = h1v[i];
            a0 = ffma2(wreg[2 * i],     v0.x, a0);
            a1 = ffma2(wreg[2 * i + 1], v0.y, a1);
            a2 = ffma2(wreg[2 * i],     v1.x, a2);
            a3 = ffma2(wreg[2 * i + 1], v1.y, a3);
        }
        {
            unsigned long long s0v = fadd2(a0, a1);
            unsigned long long s1v = fadd2(a2, a3);
            float l, h;
            unpack2(s0v, l, h); *p0 = l + h;
            unpack2(s1v, l, h); *p1 = l + h;
        }
        __syncthreads();

        if (is_gate) {
            float ghr = part[0][bb][j]          + part[1][bb][j];
            float ghz = part[0][bb][j + HH]     + part[1][bb][j + HH];
            float ghn = part[0][bb][j + 2 * HH] + part[1][bb][j + 2 * HH];
            float r = fast_sigmoid(gxr + ghr);
            float z = fast_sigmoid(gxz + ghz);
            float n = fast_tanh   (gxn + r * ghn);
            hreg = (1.0f - z) * n + z * hreg;
            hs[bb][j] = hreg;
        }
        gxr = ngxr; gxz = ngxz; gxn = ngxn;
        __syncthreads();
    }

    if (is_gate) {
        out[(size_t)(b0 + bb) * HH + j] = hreg;
    }
}

// ================= launch =================
extern "C" void kernel_launch(void* const* d_in, const int* in_sizes, int n_in,
                              void* d_out, int out_size)
{
    const float* x    = (const float*)d_in[0];
    const float* W_ih = (const float*)d_in[1];
    const float* W_hh = (const float*)d_in[2];
    const float* b_ih = (const float*)d_in[3];
    const float* b_hh = (const float*)d_in[4];
    float* out = (float*)d_out;

    size_t smem1 = (size_t)(MM * WPAD + MM * TILE_T) * sizeof(float); // ~160 KB
    cudaFuncSetAttribute(gx_kernel, cudaFuncAttributeMaxDynamicSharedMemorySize,
                         (int)smem1);

    dim3 grid1((TT + TILE_T - 1) / TILE_T, BB);
    gx_kernel<<<grid1, K1_THREADS, smem1>>>(x, W_ih, b_ih);
    gru_kernel<<<BB / 2, K2_THREADS>>>(W_hh, b_hh, out);
}

// round 4
// speedup vs baseline: 1.3190x; 1.3190x over previous
#include <cuda_runtime.h>
#include <cuda_bf16.h>
#include <cstdint>

#define BB 256
#define MM 80
#define TT 1000
#define HH 128
#define GG 384
#define TPAD 1024

// ---------------- device scratch ----------------
__device__ float g_gx[(size_t)BB * TT * GG];                // 393 MB
__device__ __nv_bfloat16 g_xhi[(size_t)BB * TPAD * MM];     // 42 MB
__device__ __nv_bfloat16 g_xlo[(size_t)BB * TPAD * MM];     // 42 MB

// ---------------- helpers ----------------
__device__ __forceinline__ unsigned long long pack2(float lo, float hi) {
    unsigned long long r;
    asm("mov.b64 %0, {%1,%2};" : "=l"(r) : "f"(lo), "f"(hi));
    return r;
}
__device__ __forceinline__ void unpack2(unsigned long long v, float& lo, float& hi) {
    asm("mov.b64 {%0,%1}, %2;" : "=f"(lo), "=f"(hi) : "l"(v));
}
__device__ __forceinline__ unsigned long long ffma2(unsigned long long a,
                                                    unsigned long long b,
                                                    unsigned long long c) {
    unsigned long long d;
    asm("fma.rn.f32x2 %0, %1, %2, %3;" : "=l"(d) : "l"(a), "l"(b), "l"(c));
    return d;
}
__device__ __forceinline__ float fast_sigmoid(float x) {
    float e = __expf(-x);
    return __fdividef(1.0f, 1.0f + e);
}
__device__ __forceinline__ float fast_tanh(float x) {
    float ax = fabsf(x);
    float e = __expf(-2.0f * ax);
    float t = __fdividef(1.0f - e, 1.0f + e);
    return copysignf(t, x);
}
__device__ __forceinline__ void cp16(uint32_t saddr, const void* g) {
    asm volatile("cp.async.cg.shared.global [%0], [%1], 16;" :: "r"(saddr), "l"(g));
}
__device__ __forceinline__ void cp_commit() { asm volatile("cp.async.commit_group;" ::: "memory"); }
__device__ __forceinline__ void cp_wait0()  { asm volatile("cp.async.wait_group 0;" ::: "memory"); }
__device__ __forceinline__ uint32_t smem_u32(const void* p) {
    uint32_t a;
    asm("{ .reg .u64 t; cvta.to.shared.u64 t, %1; cvt.u32.u64 %0, t; }" : "=r"(a) : "l"(p));
    return a;
}
__device__ __forceinline__ void mma16816(float* c, uint32_t a0, uint32_t a1,
                                         uint32_t a2, uint32_t a3,
                                         uint32_t b0, uint32_t b1) {
    asm("mma.sync.aligned.m16n8k16.row.col.f32.bf16.bf16.f32 "
        "{%0,%1,%2,%3}, {%4,%5,%6,%7}, {%8,%9}, {%0,%1,%2,%3};"
        : "+f"(c[0]), "+f"(c[1]), "+f"(c[2]), "+f"(c[3])
        : "r"(a0), "r"(a1), "r"(a2), "r"(a3), "r"(b0), "r"(b1));
}

// ================= prep: transpose + bf16 split =================
#define PREP_THREADS 256
__global__ __launch_bounds__(PREP_THREADS)
void prep_kernel(const float* __restrict__ x)
{
    __shared__ float xs[MM][129];
    const int b = blockIdx.y, t0 = blockIdx.x * 128;
    const int tid = threadIdx.x;

    for (int idx = tid; idx < MM * 128; idx += PREP_THREADS) {
        int m = idx >> 7, j = idx & 127;
        int t = t0 + j;
        xs[m][j] = (t < TT) ? x[((size_t)b * MM + m) * TT + t] : 0.0f;
    }
    __syncthreads();

    for (int idx = tid; idx < 128 * 10; idx += PREP_THREADS) {
        int j = idx / 10, mv = idx % 10;
        int m0 = mv * 8;
        __align__(16) __nv_bfloat16 hi[8];
        __align__(16) __nv_bfloat16 lo[8];
        #pragma unroll
        for (int u = 0; u < 8; u++) {
            float v = xs[m0 + u][j];
            __nv_bfloat16 h = __float2bfloat16(v);
            hi[u] = h;
            lo[u] = __float2bfloat16(v - __bfloat162float(h));
        }
        size_t off = ((size_t)b * TPAD + t0 + j) * MM + m0;
        *(uint4*)(g_xhi + off) = *(const uint4*)hi;
        *(uint4*)(g_xlo + off) = *(const uint4*)lo;
    }
}

// ================= gx via mma.sync HMMA (split-bf16, 3 terms) =================
// grid (16, 256): blockIdx.x = tt*2 + ghalf ; 256 threads (8 warps, warp owns 16 t rows)
#define GXT 256
#define A_PITCH 88     // elements; 176 B rows (16B-aligned for cp.async, conflict-free)
#define W_PITCH 84     // elements; 168 B rows (conflict-free for LDS.32)
#define SM_AHI 0
#define SM_ALO (128 * A_PITCH * 2)                    // 22528
#define SM_WHI (SM_ALO + 128 * A_PITCH * 2)           // 45056
#define SM_WLO (SM_WHI + 192 * W_PITCH * 2)           // 77312
#define GX_SMEM (SM_WLO + 192 * W_PITCH * 2)          // 109568

__device__ __forceinline__ uint32_t lds_pair(const char* base, int row, int col, int pitch) {
    return *(const uint32_t*)(base + (size_t)(row * pitch + col) * 2);
}

__global__ __launch_bounds__(GXT)
void gx_hmma_kernel(const float* __restrict__ W_ih)
{
    extern __shared__ char sm[];
    const int tid = threadIdx.x;
    const int lane = tid & 31;
    const int w = tid >> 5;
    const int grp = lane >> 2;      // 0..7
    const int q = lane & 3;         // 0..3
    const int tt = blockIdx.x >> 1;
    const int ghalf = blockIdx.x & 1;
    const int gbase = ghalf * 192;
    const int b = blockIdx.y;
    const uint32_t sb = smem_u32(sm);

    // ---- A tiles via cp.async: [128 rows][10 x 16B chunks] x {hi,lo} ----
    for (int i = tid; i < 2560; i += GXT) {
        int split = i / 1280;
        int rem = i - split * 1280;
        int row = rem / 10, ch = rem - row * 10;
        uint32_t dst = sb + (split ? SM_ALO : SM_AHI) + row * (A_PITCH * 2) + ch * 16;
        const __nv_bfloat16* src = (split ? g_xlo : g_xhi)
            + ((size_t)b * TPAD + tt * 128 + row) * MM + ch * 8;
        cp16(dst, src);
    }
    cp_commit();

    // ---- W convert: fp32 -> split bf16, [192][W_PITCH] ----
    for (int i = tid; i < 192 * MM; i += GXT) {
        int g = i / MM, m = i - g * MM;
        float v = W_ih[(size_t)(gbase + g) * MM + m];
        __nv_bfloat16 h = __float2bfloat16(v);
        __nv_bfloat16 l = __float2bfloat16(v - __bfloat162float(h));
        *(__nv_bfloat16*)(sm + SM_WHI + (size_t)(g * W_PITCH + m) * 2) = h;
        *(__nv_bfloat16*)(sm + SM_WLO + (size_t)(g * W_PITCH + m) * 2) = l;
    }
    cp_wait0();
    __syncthreads();

    // ---- A fragments in registers: [ks 0..4] x {a0,a1,a2,a3} x {hi,lo} ----
    const int r0 = w * 16 + grp;
    uint32_t ahi[20], alo[20];
    #pragma unroll
    for (int ks = 0; ks < 5; ks++) {
        int c = 16 * ks + 2 * q;
        ahi[4 * ks + 0] = lds_pair(sm + SM_AHI, r0,     c,     A_PITCH);
        ahi[4 * ks + 1] = lds_pair(sm + SM_AHI, r0 + 8, c,     A_PITCH);
        ahi[4 * ks + 2] = lds_pair(sm + SM_AHI, r0,     c + 8, A_PITCH);
        ahi[4 * ks + 3] = lds_pair(sm + SM_AHI, r0 + 8, c + 8, A_PITCH);
        alo[4 * ks + 0] = lds_pair(sm + SM_ALO, r0,     c,     A_PITCH);
        alo[4 * ks + 1] = lds_pair(sm + SM_ALO, r0 + 8, c,     A_PITCH);
        alo[4 * ks + 2] = lds_pair(sm + SM_ALO, r0,     c + 8, A_PITCH);
        alo[4 * ks + 3] = lds_pair(sm + SM_ALO, r0 + 8, c + 8, A_PITCH);
    }

    const int trow = tt * 128 + w * 16 + grp;
    float* dst = g_gx + ((size_t)b * TT + trow) * GG + gbase;
    float* dst8 = dst + 8 * GG;
    const bool v0 = (trow < TT);
    const bool v8 = (trow + 8 < TT);

    // ---- 12 gt-pairs: two n8 tiles each (g-offsets gp*16, gp*16+8) ----
    for (int gp = 0; gp < 12; gp++) {
        float acc0[4] = {0.f, 0.f, 0.f, 0.f};
        float acc1[4] = {0.f, 0.f, 0.f, 0.f};
        const int gA = gp * 16 + grp;
        const int gB = gp * 16 + 8 + grp;
        #pragma unroll
        for (int ks = 0; ks < 5; ks++) {
            int c = 16 * ks + 2 * q;
            uint32_t bh0a = lds_pair(sm + SM_WHI, gA, c,     W_PITCH);
            uint32_t bh0b = lds_pair(sm + SM_WHI, gA, c + 8, W_PITCH);
            uint32_t bh1a = lds_pair(sm + SM_WHI, gB, c,     W_PITCH);
            uint32_t bh1b = lds_pair(sm + SM_WHI, gB, c + 8, W_PITCH);
            mma16816(acc0, ahi[4*ks], ahi[4*ks+1], ahi[4*ks+2], ahi[4*ks+3], bh0a, bh0b);
            mma16816(acc1, ahi[4*ks], ahi[4*ks+1], ahi[4*ks+2], ahi[4*ks+3], bh1a, bh1b);
            mma16816(acc0, alo[4*ks], alo[4*ks+1], alo[4*ks+2], alo[4*ks+3], bh0a, bh0b);
            mma16816(acc1, alo[4*ks], alo[4*ks+1], alo[4*ks+2], alo[4*ks+3], bh1a, bh1b);
            uint32_t bl0a = lds_pair(sm + SM_WLO, gA, c,     W_PITCH);
            uint32_t bl0b = lds_pair(sm + SM_WLO, gA, c + 8, W_PITCH);
            uint32_t bl1a = lds_pair(sm + SM_WLO, gB, c,     W_PITCH);
            uint32_t bl1b = lds_pair(sm + SM_WLO, gB, c + 8, W_PITCH);
            mma16816(acc0, ahi[4*ks], ahi[4*ks+1], ahi[4*ks+2], ahi[4*ks+3], bl0a, bl0b);
            mma16816(acc1, ahi[4*ks], ahi[4*ks+1], ahi[4*ks+2], ahi[4*ks+3], bl1a, bl1b);
        }
        const int col0 = gp * 16 + 2 * q;
        if (v0) {
            *(float2*)(dst + col0)     = make_float2(acc0[0], acc0[1]);
            *(float2*)(dst + col0 + 8) = make_float2(acc1[0], acc1[1]);
        }
        if (v8) {
            *(float2*)(dst8 + col0)     = make_float2(acc0[2], acc0[3]);
            *(float2*)(dst8 + col0 + 8) = make_float2(acc1[2], acc1[3]);
        }
    }
}

// ================= gru: staggered-batch recurrence =================
// 128 blocks x 384 threads, 2 batches per block, half step out of phase.
#define K2_THREADS 384
__device__ __forceinline__ float dot_h(const unsigned long long* wreg, const float* hsv) {
    unsigned long long a0 = 0ULL, a1 = 0ULL, a2 = 0ULL, a3 = 0ULL;
    const ulonglong2* hv = (const ulonglong2*)hsv;
    #pragma unroll
    for (int i = 0; i < 16; i++) {
        ulonglong2 va = hv[2 * i];
        ulonglong2 vb = hv[2 * i + 1];
        a0 = ffma2(wreg[4 * i],     va.x, a0);
        a1 = ffma2(wreg[4 * i + 1], va.y, a1);
        a2 = ffma2(wreg[4 * i + 2], vb.x, a2);
        a3 = ffma2(wreg[4 * i + 3], vb.y, a3);
    }
    float l, h, s;
    unpack2(a0, l, h); s = l + h;
    unpack2(a1, l, h); s += l + h;
    unpack2(a2, l, h); s += l + h;
    unpack2(a3, l, h); s += l + h;
    return s;
}

__global__ __launch_bounds__(K2_THREADS, 1)
void gru_kernel(const float* __restrict__ W_hh,
                const float* __restrict__ b_ih,
                const float* __restrict__ b_hh,
                float* __restrict__ out)
{
    __shared__ __align__(16) float hs0[HH];
    __shared__ __align__(16) float hs1[HH];
    __shared__ float gh0[GG], gh1[GG];

    const int tid = threadIdx.x;
    const int g = tid;
    const int b0 = blockIdx.x * 2;

    unsigned long long wreg[HH / 2];
    {
        const float4* wr = (const float4*)(W_hh + (size_t)g * HH);
        #pragma unroll
        for (int j = 0; j < HH / 4; j++) {
            float4 v = wr[j];
            wreg[2 * j]     = pack2(v.x, v.y);
            wreg[2 * j + 1] = pack2(v.z, v.w);
        }
    }
    const float bh = b_hh[g];

    const int j = tid;                     // gate thread id (tid<128)
    const bool is_gate = (tid < HH);
    float bir = 0.f, biz = 0.f, bin = 0.f;
    float h0r = 0.f, h1r = 0.f;
    float c0r = 0.f, c0z = 0.f, c0n = 0.f, c1r = 0.f, c1z = 0.f, c1n = 0.f;
    const float* gx0p = g_gx + (size_t)b0 * TT * GG + j;
    const float* gx1p = g_gx + (size_t)(b0 + 1) * TT * GG + j;

    if (is_gate) {
        bir = b_ih[j]; biz = b_ih[j + HH]; bin = b_ih[j + 2 * HH];
        hs0[j] = 0.0f; hs1[j] = 0.0f;
        c0r = __ldg(gx0p); c0z = __ldg(gx0p + HH); c0n = __ldg(gx0p + 2 * HH);
        c1r = __ldg(gx1p); c1z = __ldg(gx1p + HH); c1n = __ldg(gx1p + 2 * HH);
    }
    gh1[g] = bh;                           // gh for h1 = 0 at step 0
    __syncthreads();

    for (int t = 0; t < TT; t++) {
        // ---------- phase A: dot b0 | gates b1 ----------
        float n0r = 0.f, n0z = 0.f, n0n = 0.f, n1r = 0.f, n1z = 0.f, n1n = 0.f;
        if (is_gate) {
            const int tn = (t + 1 < TT) ? (t + 1) : (TT - 1);
            const float* p0 = gx0p + (size_t)tn * GG;
            const float* p1 = gx1p + (size_t)tn * GG;
            n0r = __ldg(p0); n0z = __ldg(p0 + HH); n0n = __ldg(p0 + 2 * HH);
            n1r = __ldg(p1); n1z = __ldg(p1 + HH); n1n = __ldg(p1 + 2 * HH);
        }

        float s0 = dot_h(wreg, hs0);
        if (is_gate) {
            float r = fast_sigmoid(c1r + bir + gh1[j]);
            float z = fast_sigmoid(c1z + biz + gh1[j + HH]);
            float n = fast_tanh(c1n + bin + r * gh1[j + 2 * HH]);
            h1r = (1.0f - z) * n + z * h1r;
            hs1[j] = h1r;
        }
        gh0[g] = s0 + bh;
        __syncthreads();

        // ---------- phase B: dot b1 | gates b0 ----------
        float s1 = dot_h(wreg, hs1);
        if (is_gate) {
            float r = fast_sigmoid(c0r + bir + gh0[j]);
            float z = fast_sigmoid(c0z + biz + gh0[j + HH]);
            float n = fast_tanh(c0n + bin + r * gh0[j + 2 * HH]);
            h0r = (1.0f - z) * n + z * h0r;
            hs0[j] = h0r;
        }
        gh1[g] = s1 + bh;
        c0r = n0r; c0z = n0z; c0n = n0n;
        c1r = n1r; c1z = n1z; c1n = n1n;
        __syncthreads();
    }

    if (is_gate) {
        out[(size_t)b0 * HH + j] = h0r;
        out[(size_t)(b0 + 1) * HH + j] = h1r;
    }
}

// ================= launch =================
extern "C" void kernel_launch(void* const* d_in, const int* in_sizes, int n_in,
                              void* d_out, int out_size)
{
    const float* x    = (const float*)d_in[0];
    const float* W_ih = (const float*)d_in[1];
    const float* W_hh = (const float*)d_in[2];
    const float* b_ih = (const float*)d_in[3];
    const float* b_hh = (const float*)d_in[4];
    float* out = (float*)d_out;

    cudaFuncSetAttribute(gx_hmma_kernel,
                         cudaFuncAttributeMaxDynamicSharedMemorySize, GX_SMEM);

    prep_kernel<<<dim3(8, BB), PREP_THREADS>>>(x);
    gx_hmma_kernel<<<dim3(16, BB), GXT, GX_SMEM>>>(W_ih);
    gru_kernel<<<BB / 2, K2_THREADS>>>(W_hh, b_ih, b_hh, out);
}

// round 5
// speedup vs baseline: 1.5808x; 1.1985x over previous
#include <cuda_runtime.h>
#include <cuda_bf16.h>
#include <cstdint>

#define BB 256
#define MM 80
#define TT 1000
#define HH 128
#define GG 384
#define TPAD 1024

// ---------------- device scratch ----------------
__device__ float g_gx[(size_t)BB * TT * GG];                // 393 MB
__device__ __nv_bfloat16 g_xhi[(size_t)BB * TPAD * MM];     // 42 MB
__device__ __nv_bfloat16 g_xlo[(size_t)BB * TPAD * MM];     // 42 MB

// ---------------- helpers ----------------
__device__ __forceinline__ float fast_sigmoid(float x) {
    float e = __expf(-x);
    return __fdividef(1.0f, 1.0f + e);
}
__device__ __forceinline__ float fast_tanh(float x) {
    float ax = fabsf(x);
    float e = __expf(-2.0f * ax);
    float t = __fdividef(1.0f - e, 1.0f + e);
    return copysignf(t, x);
}
__device__ __forceinline__ void cp16(uint32_t saddr, const void* g) {
    asm volatile("cp.async.cg.shared.global [%0], [%1], 16;" :: "r"(saddr), "l"(g));
}
__device__ __forceinline__ void cp_commit() { asm volatile("cp.async.commit_group;" ::: "memory"); }
__device__ __forceinline__ void cp_wait0()  { asm volatile("cp.async.wait_group 0;" ::: "memory"); }
__device__ __forceinline__ uint32_t smem_u32(const void* p) {
    uint32_t a;
    asm("{ .reg .u64 t; cvta.to.shared.u64 t, %1; cvt.u32.u64 %0, t; }" : "=r"(a) : "l"(p));
    return a;
}
__device__ __forceinline__ void mma16816(float* c, uint32_t a0, uint32_t a1,
                                         uint32_t a2, uint32_t a3,
                                         uint32_t b0, uint32_t b1) {
    asm("mma.sync.aligned.m16n8k16.row.col.f32.bf16.bf16.f32 "
        "{%0,%1,%2,%3}, {%4,%5,%6,%7}, {%8,%9}, {%0,%1,%2,%3};"
        : "+f"(c[0]), "+f"(c[1]), "+f"(c[2]), "+f"(c[3])
        : "r"(a0), "r"(a1), "r"(a2), "r"(a3), "r"(b0), "r"(b1));
}
__device__ __forceinline__ uint32_t bf16_hi_pack(float a, float b) {
    uint32_t ua = (uint32_t)__bfloat16_as_ushort(__float2bfloat16(a));
    uint32_t ub = (uint32_t)__bfloat16_as_ushort(__float2bfloat16(b));
    return ua | (ub << 16);
}
__device__ __forceinline__ uint32_t bf16_lo_pack(float a, float b) {
    float ra = a - __bfloat162float(__float2bfloat16(a));
    float rb = b - __bfloat162float(__float2bfloat16(b));
    return bf16_hi_pack(ra, rb);
}

// ================= prep: transpose + bf16 split =================
#define PREP_THREADS 256
__global__ __launch_bounds__(PREP_THREADS)
void prep_kernel(const float* __restrict__ x)
{
    __shared__ float xs[MM][129];
    const int b = blockIdx.y, t0 = blockIdx.x * 128;
    const int tid = threadIdx.x;

    for (int idx = tid; idx < MM * 128; idx += PREP_THREADS) {
        int m = idx >> 7, j = idx & 127;
        int t = t0 + j;
        xs[m][j] = (t < TT) ? x[((size_t)b * MM + m) * TT + t] : 0.0f;
    }
    __syncthreads();

    for (int idx = tid; idx < 128 * 10; idx += PREP_THREADS) {
        int j = idx / 10, mv = idx % 10;
        int m0 = mv * 8;
        __align__(16) __nv_bfloat16 hi[8];
        __align__(16) __nv_bfloat16 lo[8];
        #pragma unroll
        for (int u = 0; u < 8; u++) {
            float v = xs[m0 + u][j];
            __nv_bfloat16 h = __float2bfloat16(v);
            hi[u] = h;
            lo[u] = __float2bfloat16(v - __bfloat162float(h));
        }
        size_t off = ((size_t)b * TPAD + t0 + j) * MM + m0;
        *(uint4*)(g_xhi + off) = *(const uint4*)hi;
        *(uint4*)(g_xlo + off) = *(const uint4*)lo;
    }
}

// ================= gx via mma.sync HMMA (split-bf16, 3 terms) =================
#define GXT 256
#define A_PITCH 88
#define W_PITCH 84
#define SM_AHI 0
#define SM_ALO (128 * A_PITCH * 2)
#define SM_WHI (SM_ALO + 128 * A_PITCH * 2)
#define SM_WLO (SM_WHI + 192 * W_PITCH * 2)
#define GX_SMEM (SM_WLO + 192 * W_PITCH * 2)

__device__ __forceinline__ uint32_t lds_pair(const char* base, int row, int col, int pitch) {
    return *(const uint32_t*)(base + (size_t)(row * pitch + col) * 2);
}

__global__ __launch_bounds__(GXT)
void gx_hmma_kernel(const float* __restrict__ W_ih)
{
    extern __shared__ char sm[];
    const int tid = threadIdx.x;
    const int lane = tid & 31;
    const int w = tid >> 5;
    const int grp = lane >> 2;
    const int q = lane & 3;
    const int tt = blockIdx.x >> 1;
    const int ghalf = blockIdx.x & 1;
    const int gbase = ghalf * 192;
    const int b = blockIdx.y;
    const uint32_t sb = smem_u32(sm);

    for (int i = tid; i < 2560; i += GXT) {
        int split = i / 1280;
        int rem = i - split * 1280;
        int row = rem / 10, ch = rem - row * 10;
        uint32_t dst = sb + (split ? SM_ALO : SM_AHI) + row * (A_PITCH * 2) + ch * 16;
        const __nv_bfloat16* src = (split ? g_xlo : g_xhi)
            + ((size_t)b * TPAD + tt * 128 + row) * MM + ch * 8;
        cp16(dst, src);
    }
    cp_commit();

    for (int i = tid; i < 192 * MM; i += GXT) {
        int g = i / MM, m = i - g * MM;
        float v = W_ih[(size_t)(gbase + g) * MM + m];
        __nv_bfloat16 h = __float2bfloat16(v);
        __nv_bfloat16 l = __float2bfloat16(v - __bfloat162float(h));
        *(__nv_bfloat16*)(sm + SM_WHI + (size_t)(g * W_PITCH + m) * 2) = h;
        *(__nv_bfloat16*)(sm + SM_WLO + (size_t)(g * W_PITCH + m) * 2) = l;
    }
    cp_wait0();
    __syncthreads();

    const int r0 = w * 16 + grp;
    uint32_t ahi[20], alo[20];
    #pragma unroll
    for (int ks = 0; ks < 5; ks++) {
        int c = 16 * ks + 2 * q;
        ahi[4 * ks + 0] = lds_pair(sm + SM_AHI, r0,     c,     A_PITCH);
        ahi[4 * ks + 1] = lds_pair(sm + SM_AHI, r0 + 8, c,     A_PITCH);
        ahi[4 * ks + 2] = lds_pair(sm + SM_AHI, r0,     c + 8, A_PITCH);
        ahi[4 * ks + 3] = lds_pair(sm + SM_AHI, r0 + 8, c + 8, A_PITCH);
        alo[4 * ks + 0] = lds_pair(sm + SM_ALO, r0,     c,     A_PITCH);
        alo[4 * ks + 1] = lds_pair(sm + SM_ALO, r0 + 8, c,     A_PITCH);
        alo[4 * ks + 2] = lds_pair(sm + SM_ALO, r0,     c + 8, A_PITCH);
        alo[4 * ks + 3] = lds_pair(sm + SM_ALO, r0 + 8, c + 8, A_PITCH);
    }

    const int trow = tt * 128 + w * 16 + grp;
    float* dst = g_gx + ((size_t)b * TT + trow) * GG + gbase;
    float* dst8 = dst + 8 * GG;
    const bool v0 = (trow < TT);
    const bool v8 = (trow + 8 < TT);

    for (int gp = 0; gp < 12; gp++) {
        float acc0[4] = {0.f, 0.f, 0.f, 0.f};
        float acc1[4] = {0.f, 0.f, 0.f, 0.f};
        const int gA = gp * 16 + grp;
        const int gB = gp * 16 + 8 + grp;
        #pragma unroll
        for (int ks = 0; ks < 5; ks++) {
            int c = 16 * ks + 2 * q;
            uint32_t bh0a = lds_pair(sm + SM_WHI, gA, c,     W_PITCH);
            uint32_t bh0b = lds_pair(sm + SM_WHI, gA, c + 8, W_PITCH);
            uint32_t bh1a = lds_pair(sm + SM_WHI, gB, c,     W_PITCH);
            uint32_t bh1b = lds_pair(sm + SM_WHI, gB, c + 8, W_PITCH);
            mma16816(acc0, ahi[4*ks], ahi[4*ks+1], ahi[4*ks+2], ahi[4*ks+3], bh0a, bh0b);
            mma16816(acc1, ahi[4*ks], ahi[4*ks+1], ahi[4*ks+2], ahi[4*ks+3], bh1a, bh1b);
            mma16816(acc0, alo[4*ks], alo[4*ks+1], alo[4*ks+2], alo[4*ks+3], bh0a, bh0b);
            mma16816(acc1, alo[4*ks], alo[4*ks+1], alo[4*ks+2], alo[4*ks+3], bh1a, bh1b);
            uint32_t bl0a = lds_pair(sm + SM_WLO, gA, c,     W_PITCH);
            uint32_t bl0b = lds_pair(sm + SM_WLO, gA, c + 8, W_PITCH);
            uint32_t bl1a = lds_pair(sm + SM_WLO, gB, c,     W_PITCH);
            uint32_t bl1b = lds_pair(sm + SM_WLO, gB, c + 8, W_PITCH);
            mma16816(acc0, ahi[4*ks], ahi[4*ks+1], ahi[4*ks+2], ahi[4*ks+3], bl0a, bl0b);
            mma16816(acc1, ahi[4*ks], ahi[4*ks+1], ahi[4*ks+2], ahi[4*ks+3], bl1a, bl1b);
        }
        const int col0 = gp * 16 + 2 * q;
        if (v0) {
            *(float2*)(dst + col0)     = make_float2(acc0[0], acc0[1]);
            *(float2*)(dst + col0 + 8) = make_float2(acc1[0], acc1[1]);
        }
        if (v8) {
            *(float2*)(dst8 + col0)     = make_float2(acc0[2], acc0[3]);
            *(float2*)(dst8 + col0 + 8) = make_float2(acc1[2], acc1[3]);
        }
    }
}

// ================= gru: 8-batch HMMA recurrence =================
// 32 blocks x 512 threads. Warps 0..11: mma (each 2 m-tiles = 32 g-rows).
// All 512 threads: gates, one j-pair each (b = tid>>6, j = 2*(tid&63)).
// smem (uint32 words): wlo2[384][68] | hsh[8][68] | hsl[8][68] | ghs[8][388] (float)
#define GRUT 512
#define WLO_W (384 * 68)
#define HSH_W WLO_W
#define HSL_W (HSH_W + 8 * 68)
#define GHS_W (HSL_W + 8 * 68)
#define GRU_SMEM ((GHS_W + 8 * 388) * 4)

__global__ __launch_bounds__(GRUT, 1)
void gru_hmma_kernel(const float* __restrict__ W_hh,
                     const float* __restrict__ b_ih,
                     const float* __restrict__ b_hh,
                     float* __restrict__ out)
{
    extern __shared__ uint32_t dsm[];
    uint32_t* wlo2 = dsm;
    uint32_t* hsh  = dsm + HSH_W;
    uint32_t* hsl  = dsm + HSL_W;
    float*    ghs  = (float*)(dsm + GHS_W);

    const int tid = threadIdx.x;
    const int lane = tid & 31;
    const int wid = tid >> 5;
    const int grp = lane >> 2;
    const int q = lane & 3;
    const int b0 = blockIdx.x * 8;
    const bool mma_warp = (wid < 12);
    const int m0 = wid * 32;               // base g-row for this mma warp

    // ---- W_hi fragments in registers ----
    uint32_t whi[2][8][4];
    if (mma_warp) {
        #pragma unroll
        for (int mt = 0; mt < 2; mt++) {
            #pragma unroll
            for (int kt = 0; kt < 8; kt++) {
                #pragma unroll
                for (int r = 0; r < 4; r++) {
                    int row = m0 + mt * 16 + grp + (r & 1) * 8;
                    int col = kt * 16 + 2 * q + (r >> 1) * 8;
                    float f0 = __ldg(W_hh + (size_t)row * HH + col);
                    float f1 = __ldg(W_hh + (size_t)row * HH + col + 1);
                    whi[mt][kt][r] = bf16_hi_pack(f0, f1);
                }
            }
        }
    }

    // ---- W_lo into smem [384][68] (bf16x2 per k-pair) ----
    for (int idx = tid; idx < 384 * 64; idx += GRUT) {
        int m = idx >> 6, kp = idx & 63;
        float f0 = W_hh[(size_t)m * HH + 2 * kp];
        float f1 = W_hh[(size_t)m * HH + 2 * kp + 1];
        wlo2[m * 68 + kp] = bf16_lo_pack(f0, f1);
    }
    // h0 = 0
    for (int idx = tid; idx < 2 * 8 * 68; idx += GRUT) {
        dsm[HSH_W + idx] = 0u;
    }

    // ---- gate-role setup ----
    const int gb = tid >> 6;               // batch 0..7
    const int jp = tid & 63;
    const int j = 2 * jp;
    float br0 = b_ih[j] + b_hh[j];
    float br1 = b_ih[j + 1] + b_hh[j + 1];
    float bz0 = b_ih[HH + j] + b_hh[HH + j];
    float bz1 = b_ih[HH + j + 1] + b_hh[HH + j + 1];
    float bin0 = b_ih[2 * HH + j],     bhn0 = b_hh[2 * HH + j];
    float bin1 = b_ih[2 * HH + j + 1], bhn1 = b_hh[2 * HH + j + 1];
    float hj = 0.0f, hj1 = 0.0f;

    const float* gxp = g_gx + ((size_t)(b0 + gb) * TT) * GG + j;
    float2 cr = __ldg((const float2*)(gxp));
    float2 cz = __ldg((const float2*)(gxp + HH));
    float2 cn = __ldg((const float2*)(gxp + 2 * HH));
    __syncthreads();

    for (int t = 0; t < TT; t++) {
        // prefetch next step's gx (hidden under mma phase)
        const size_t tn = (t + 1 < TT) ? (size_t)(t + 1) : (size_t)t;
        const float* pn = gxp + tn * GG;
        float2 nr = __ldg((const float2*)(pn));
        float2 nz = __ldg((const float2*)(pn + HH));
        float2 nn = __ldg((const float2*)(pn + 2 * HH));

        if (mma_warp) {
            float C0[4] = {0.f, 0.f, 0.f, 0.f};
            float C1[4] = {0.f, 0.f, 0.f, 0.f};
            #pragma unroll
            for (int kt = 0; kt < 8; kt++) {
                uint32_t bh0 = hsh[grp * 68 + kt * 8 + q];
                uint32_t bh1 = hsh[grp * 68 + kt * 8 + q + 4];
                uint32_t bl0 = hsl[grp * 68 + kt * 8 + q];
                uint32_t bl1 = hsl[grp * 68 + kt * 8 + q + 4];
                // Whi * hhi
                mma16816(C0, whi[0][kt][0], whi[0][kt][1], whi[0][kt][2], whi[0][kt][3], bh0, bh1);
                mma16816(C1, whi[1][kt][0], whi[1][kt][1], whi[1][kt][2], whi[1][kt][3], bh0, bh1);
                // Whi * hlo
                mma16816(C0, whi[0][kt][0], whi[0][kt][1], whi[0][kt][2], whi[0][kt][3], bl0, bl1);
                mma16816(C1, whi[1][kt][0], whi[1][kt][1], whi[1][kt][2], whi[1][kt][3], bl0, bl1);
                // Wlo * hhi (fragments from smem)
                {
                    uint32_t w0 = wlo2[(m0 + grp) * 68 + kt * 8 + q];
                    uint32_t w1 = wlo2[(m0 + grp + 8) * 68 + kt * 8 + q];
                    uint32_t w2 = wlo2[(m0 + grp) * 68 + kt * 8 + q + 4];
                    uint32_t w3 = wlo2[(m0 + grp + 8) * 68 + kt * 8 + q + 4];
                    mma16816(C0, w0, w1, w2, w3, bh0, bh1);
                }
                {
                    uint32_t w0 = wlo2[(m0 + 16 + grp) * 68 + kt * 8 + q];
                    uint32_t w1 = wlo2[(m0 + 24 + grp) * 68 + kt * 8 + q];
                    uint32_t w2 = wlo2[(m0 + 16 + grp) * 68 + kt * 8 + q + 4];
                    uint32_t w3 = wlo2[(m0 + 24 + grp) * 68 + kt * 8 + q + 4];
                    mma16816(C1, w0, w1, w2, w3, bh0, bh1);
                }
            }
            // gh -> smem, n-major [8][388]
            ghs[(2 * q)     * 388 + m0 + grp]      = C0[0];
            ghs[(2 * q + 1) * 388 + m0 + grp]      = C0[1];
            ghs[(2 * q)     * 388 + m0 + grp + 8]  = C0[2];
            ghs[(2 * q + 1) * 388 + m0 + grp + 8]  = C0[3];
            ghs[(2 * q)     * 388 + m0 + 16 + grp]     = C1[0];
            ghs[(2 * q + 1) * 388 + m0 + 16 + grp]     = C1[1];
            ghs[(2 * q)     * 388 + m0 + 16 + grp + 8] = C1[2];
            ghs[(2 * q + 1) * 388 + m0 + 16 + grp + 8] = C1[3];
        }
        __syncthreads();

        // ---- gates: one j-pair per thread ----
        {
            float2 ghr = *(const float2*)&ghs[gb * 388 + j];
            float2 ghz = *(const float2*)&ghs[gb * 388 + HH + j];
            float2 ghn = *(const float2*)&ghs[gb * 388 + 2 * HH + j];
            float r0 = fast_sigmoid(cr.x + br0 + ghr.x);
            float r1 = fast_sigmoid(cr.y + br1 + ghr.y);
            float z0 = fast_sigmoid(cz.x + bz0 + ghz.x);
            float z1 = fast_sigmoid(cz.y + bz1 + ghz.y);
            float n0 = fast_tanh(cn.x + bin0 + r0 * (ghn.x + bhn0));
            float n1 = fast_tanh(cn.y + bin1 + r1 * (ghn.y + bhn1));
            hj  = (1.0f - z0) * n0 + z0 * hj;
            hj1 = (1.0f - z1) * n1 + z1 * hj1;
            hsh[gb * 68 + jp] = bf16_hi_pack(hj, hj1);
            hsl[gb * 68 + jp] = bf16_lo_pack(hj, hj1);
        }
        cr = nr; cz = nz; cn = nn;
        __syncthreads();
    }

    *(float2*)(out + (size_t)(b0 + gb) * HH + j) = make_float2(hj, hj1);
}

// ================= launch =================
extern "C" void kernel_launch(void* const* d_in, const int* in_sizes, int n_in,
                              void* d_out, int out_size)
{
    const float* x    = (const float*)d_in[0];
    const float* W_ih = (const float*)d_in[1];
    const float* W_hh = (const float*)d_in[2];
    const float* b_ih = (const float*)d_in[3];
    const float* b_hh = (const float*)d_in[4];
    float* out = (float*)d_out;

    cudaFuncSetAttribute(gx_hmma_kernel,
                         cudaFuncAttributeMaxDynamicSharedMemorySize, GX_SMEM);
    cudaFuncSetAttribute(gru_hmma_kernel,
                         cudaFuncAttributeMaxDynamicSharedMemorySize, GRU_SMEM);

    prep_kernel<<<dim3(8, BB), PREP_THREADS>>>(x);
    gx_hmma_kernel<<<dim3(16, BB), GXT, GX_SMEM>>>(W_ih);
    gru_hmma_kernel<<<BB / 8, GRUT, GRU_SMEM>>>(W_hh, b_ih, b_hh, out);
}